// round 1
// baseline (speedup 1.0000x reference)
#include <cuda_runtime.h>
#include <math.h>

// ---------------------------------------------------------------------------
// Problem constants
// ---------------------------------------------------------------------------
constexpr int B   = 2;
constexpr int N   = 2048;
constexpr int C   = 1024;
constexpr int H   = 16;
constexpr int D   = 64;       // C / H
constexpr int DFF = 4096;     // 4 * C
constexpr int BN_ROWS = B * N;        // 4096
constexpr float EPS = 1e-5f;
constexpr float SCALE = 0.125f;       // D^-0.5 = 1/8

// ---------------------------------------------------------------------------
// Scratch (device globals; no allocations allowed)
// ---------------------------------------------------------------------------
__device__ float g_xn[BN_ROWS * C];         // ln1(x) / ln2(x1) (reused)
__device__ float g_qkv[BN_ROWS * 3 * C];    // qkv projection
__device__ float g_attnout[BN_ROWS * C];    // attn @ v, heads merged
__device__ float g_x1[BN_ROWS * C];         // x + proj(attnout)
__device__ float g_h[BN_ROWS * DFF];        // gelu(fc1)

// ---------------------------------------------------------------------------
// LayerNorm: one block per row, row cached in shared
// ---------------------------------------------------------------------------
__global__ void ln_kernel(const float* __restrict__ x,
                          const float* __restrict__ g,
                          const float* __restrict__ b,
                          float* __restrict__ out) {
    const int row = blockIdx.x;
    const int tid = threadIdx.x;
    const float* xr = x + (size_t)row * C;

    __shared__ float sdata[C];
    __shared__ float red[256];

    float lsum = 0.f;
    for (int i = tid; i < C; i += 256) {
        float v = xr[i];
        sdata[i] = v;
        lsum += v;
    }
    red[tid] = lsum;
    __syncthreads();
    for (int s = 128; s > 0; s >>= 1) {
        if (tid < s) red[tid] += red[tid + s];
        __syncthreads();
    }
    const float mu = red[0] * (1.0f / C);
    __syncthreads();

    float lvar = 0.f;
    for (int i = tid; i < C; i += 256) {
        float d = sdata[i] - mu;
        lvar += d * d;
    }
    red[tid] = lvar;
    __syncthreads();
    for (int s = 128; s > 0; s >>= 1) {
        if (tid < s) red[tid] += red[tid + s];
        __syncthreads();
    }
    const float rstd = rsqrtf(red[0] * (1.0f / C) + EPS);

    float* outr = out + (size_t)row * C;
    for (int i = tid; i < C; i += 256) {
        outr[i] = (sdata[i] - mu) * rstd * g[i] + b[i];
    }
}

// ---------------------------------------------------------------------------
// Tiled SGEMM: C = alpha * A * op(B) (+ epilogue)
//   A: [M,K] row-major, lda
//   TRANSB=true : B is [Nc,K] row-major (NT, torch Linear weights)
//   TRANSB=false: B is [K,Nc] row-major (NN)
// Batched over blockIdx.z with (b,h) decomposition: off = b*s?b + h*s?h
// EPI: 0 = none, 2 = +bias +resid, 3 = +bias, exact GELU
// Tiles: 64x64x16, 256 threads, 4x4 per thread. All dims divide exactly.
// ---------------------------------------------------------------------------
__device__ __forceinline__ float gelu_exact(float v) {
    return 0.5f * v * (1.0f + erff(v * 0.70710678118654752f));
}

template<bool TRANSB, int EPI>
__global__ void __launch_bounds__(256)
gemm64(const float* __restrict__ A, int lda, long long sAb, long long sAh,
       const float* __restrict__ Bp, int ldb, long long sBb, long long sBh,
       float* __restrict__ Cp, int ldc, long long sCb, long long sCh,
       int K, float alpha, int nH,
       const float* __restrict__ bias,
       const float* __restrict__ resid, int ldres, long long sRb, long long sRh) {
    const int z  = blockIdx.z;
    const int bz = z / nH;
    const int hz = z % nH;
    A  += (size_t)bz * sAb + (size_t)hz * sAh;
    Bp += (size_t)bz * sBb + (size_t)hz * sBh;
    Cp += (size_t)bz * sCb + (size_t)hz * sCh;
    if (EPI == 2) resid += (size_t)bz * sRb + (size_t)hz * sRh;

    __shared__ float As[16][64];
    __shared__ float Bs[16][64];

    const int tid  = threadIdx.x;
    const int tcol = tid & 15;   // 16 col groups
    const int trow = tid >> 4;   // 16 row groups

    const int m0 = blockIdx.y * 64;
    const int n0 = blockIdx.x * 64;

    float acc[4][4] = {};

    for (int k0 = 0; k0 < K; k0 += 16) {
        // load A tile 64x16 -> As[k][m]
        #pragma unroll
        for (int i = tid; i < 1024; i += 256) {
            int r = i >> 4, c = i & 15;
            As[c][r] = A[(size_t)(m0 + r) * lda + (k0 + c)];
        }
        if (TRANSB) {
            #pragma unroll
            for (int i = tid; i < 1024; i += 256) {
                int r = i >> 4, c = i & 15;
                Bs[c][r] = Bp[(size_t)(n0 + r) * ldb + (k0 + c)];
            }
        } else {
            #pragma unroll
            for (int i = tid; i < 1024; i += 256) {
                int r = i >> 6, c = i & 63;
                Bs[r][c] = Bp[(size_t)(k0 + r) * ldb + (n0 + c)];
            }
        }
        __syncthreads();

        #pragma unroll
        for (int k = 0; k < 16; k++) {
            float4 av = *reinterpret_cast<const float4*>(&As[k][trow * 4]);
            float4 bv = *reinterpret_cast<const float4*>(&Bs[k][tcol * 4]);
            float a[4] = {av.x, av.y, av.z, av.w};
            float bq[4] = {bv.x, bv.y, bv.z, bv.w};
            #pragma unroll
            for (int i = 0; i < 4; i++)
                #pragma unroll
                for (int j = 0; j < 4; j++)
                    acc[i][j] += a[i] * bq[j];
        }
        __syncthreads();
    }

    // epilogue
    #pragma unroll
    for (int i = 0; i < 4; i++) {
        const int r = m0 + trow * 4 + i;
        #pragma unroll
        for (int j = 0; j < 4; j++) {
            const int cI = n0 + tcol * 4 + j;
            float v = acc[i][j] * alpha;
            if (EPI == 2) v += bias[cI] + resid[(size_t)r * ldres + cI];
            if (EPI == 3) v = gelu_exact(v + bias[cI]);
            Cp[(size_t)r * ldc + cI] = v;
        }
    }
}

// ---------------------------------------------------------------------------
// Masked in-place softmax over rows of attn [B*H*N, N]
// ---------------------------------------------------------------------------
__global__ void softmax_kernel(float* __restrict__ attn,
                               const int* __restrict__ mask) {
    const long long row = blockIdx.x;           // over B*H*N
    const int b = (int)(row / ((long long)H * N));
    float* p = attn + row * (long long)N;
    const int* mrow = mask + (size_t)b * N;
    const int tid = threadIdx.x;

    __shared__ float red[256];

    float vals[8];  // N / 256 = 8
    float lmax = -INFINITY;
    #pragma unroll
    for (int j = 0; j < 8; j++) {
        int i = tid + j * 256;
        float v = mrow[i] ? p[i] : -INFINITY;
        vals[j] = v;
        lmax = fmaxf(lmax, v);
    }
    red[tid] = lmax;
    __syncthreads();
    for (int s = 128; s > 0; s >>= 1) {
        if (tid < s) red[tid] = fmaxf(red[tid], red[tid + s]);
        __syncthreads();
    }
    const float rowmax = red[0];
    __syncthreads();

    float lsum = 0.f;
    #pragma unroll
    for (int j = 0; j < 8; j++) {
        float e = __expf(vals[j] - rowmax);
        vals[j] = e;
        lsum += e;
    }
    red[tid] = lsum;
    __syncthreads();
    for (int s = 128; s > 0; s >>= 1) {
        if (tid < s) red[tid] += red[tid + s];
        __syncthreads();
    }
    const float inv = 1.0f / red[0];

    #pragma unroll
    for (int j = 0; j < 8; j++) {
        p[tid + j * 256] = vals[j] * inv;
    }
}

// ---------------------------------------------------------------------------
// Host launcher
// ---------------------------------------------------------------------------
extern "C" void kernel_launch(void* const* d_in, const int* in_sizes, int n_in,
                              void* d_out, int out_size) {
    const float* x      = (const float*)d_in[0];
    const int*   mask   = (const int*)  d_in[1];
    const float* qkv_w  = (const float*)d_in[2];
    const float* proj_w = (const float*)d_in[3];
    const float* proj_b = (const float*)d_in[4];
    const float* ln1_g  = (const float*)d_in[5];
    const float* ln1_b  = (const float*)d_in[6];
    const float* ln2_g  = (const float*)d_in[7];
    const float* ln2_b  = (const float*)d_in[8];
    const float* fc1_w  = (const float*)d_in[9];
    const float* fc1_b  = (const float*)d_in[10];
    const float* fc2_w  = (const float*)d_in[11];
    const float* fc2_b  = (const float*)d_in[12];

    float* out_x    = (float*)d_out;
    float* out_attn = out_x + (size_t)B * N * C;

    float *xn, *qkv, *attnout, *x1, *hbuf;
    cudaGetSymbolAddress((void**)&xn,      g_xn);
    cudaGetSymbolAddress((void**)&qkv,     g_qkv);
    cudaGetSymbolAddress((void**)&attnout, g_attnout);
    cudaGetSymbolAddress((void**)&x1,      g_x1);
    cudaGetSymbolAddress((void**)&hbuf,    g_h);

    const long long sQKVb = (long long)N * 3 * C;  // batch stride in qkv buffer
    const long long sAttb = (long long)H * N * N;
    const long long sAtth = (long long)N * N;

    // 1) ln1(x) -> xn
    ln_kernel<<<BN_ROWS, 256>>>(x, ln1_g, ln1_b, xn);

    // 2) qkv = xn @ qkv_w^T   [4096,1024]x[3072,1024]^T -> [4096,3072]
    gemm64<true, 0><<<dim3(3 * C / 64, BN_ROWS / 64, 1), 256>>>(
        xn, C, 0, 0,
        qkv_w, C, 0, 0,
        qkv, 3 * C, 0, 0,
        C, 1.0f, 1, nullptr, nullptr, 0, 0, 0);

    // 3) scores = scale * Q @ K^T  (batched over B*H), written into out_attn
    gemm64<true, 0><<<dim3(N / 64, N / 64, B * H), 256>>>(
        qkv,          3 * C, sQKVb, D,        // Q: off h*D
        qkv + C,      3 * C, sQKVb, D,        // K: off C + h*D
        out_attn,     N,     sAttb, sAtth,
        D, SCALE, H, nullptr, nullptr, 0, 0, 0);

    // 4) masked softmax in place
    softmax_kernel<<<B * H * N, 256>>>(out_attn, mask);

    // 5) attnout = attn @ V (batched, NN), heads merged into [B*N, C]
    gemm64<false, 0><<<dim3(1, N / 64, B * H), 256>>>(
        out_attn,      N,     sAttb, sAtth,
        qkv + 2 * C,   3 * C, sQKVb, D,
        attnout,       C,     (long long)N * C, D,
        N, 1.0f, H, nullptr, nullptr, 0, 0, 0);

    // 6) x1 = x + attnout @ proj_w^T + proj_b
    gemm64<true, 2><<<dim3(C / 64, BN_ROWS / 64, 1), 256>>>(
        attnout, C, 0, 0,
        proj_w,  C, 0, 0,
        x1,      C, 0, 0,
        C, 1.0f, 1, proj_b, x, C, 0, 0);

    // 7) ln2(x1) -> xn (reuse)
    ln_kernel<<<BN_ROWS, 256>>>(x1, ln2_g, ln2_b, xn);

    // 8) h = gelu(xn @ fc1_w^T + fc1_b)
    gemm64<true, 3><<<dim3(DFF / 64, BN_ROWS / 64, 1), 256>>>(
        xn,    C, 0, 0,
        fc1_w, C, 0, 0,
        hbuf,  DFF, 0, 0,
        C, 1.0f, 1, fc1_b, nullptr, 0, 0, 0);

    // 9) out_x = x1 + h @ fc2_w^T + fc2_b
    gemm64<true, 2><<<dim3(C / 64, BN_ROWS / 64, 1), 256>>>(
        hbuf,  DFF, 0, 0,
        fc2_w, DFF, 0, 0,
        out_x, C, 0, 0,
        DFF, 1.0f, 1, fc2_b, x1, C, 0, 0);
}